// round 2
// baseline (speedup 1.0000x reference)
#include <cuda_runtime.h>

// ---------------- problem dims ----------------
#define NWIN   4096          // B_ windows
#define NGT    49            // tokens per window
#define NTOK   50            // +1 global token
#define CDIM   128
#define HEADS  4
#define HD     32
#define BIMG   64
#define NTPAT  3136
#define WQ_SCALE 0.17677669529663687f   // 32^-0.5

// ---------------- device scratch (no cudaMalloc allowed) ----------------
__device__ float g_Q [200704u * 128u];   // (4096*49, 128)  scaled q
__device__ float g_Kw[204800u * 128u];   // (4096*50, 128)  window K (row 49 = global tok)
__device__ float g_Vw[204800u * 128u];   // (4096*50, 128)  window V
__device__ float g_Kg[200704u * 128u];   // (64*3136, 128)  global K
__device__ float g_Vg[200704u * 128u];   // (64*3136, 128)  global V
__device__ float g_bias[HEADS * NGT * NTOK];   // (4,49,50)

// ---------------- SGEMM: C[M,128|256] = (A[M,128] @ W[128,N] + b) * alpha ----
// BM=128, BN=128, BK=8, 256 threads, 8x8 register tile per thread.
// GATHER=1: A rows are the window-concat rows (49 window tokens + xavg row).
// DST: 0 -> g_Q, 1 -> g_Kw/g_Vw (by blockIdx.x half), 2 -> g_Kg/g_Vg.
template<int GATHER, int DST>
__global__ void __launch_bounds__(256)
sgemm_kernel(const float* __restrict__ A, const float* __restrict__ Aavg,
             const float* __restrict__ W, const float* __restrict__ bias,
             int N, float alpha)
{
    __shared__ float As[8][132];   // [k][m] transposed, padded
    __shared__ float Bs[8][128];   // [k][n]

    const int tid = threadIdx.x;
    const int bx  = blockIdx.x;          // n-block (0 or 1)
    const int by  = blockIdx.y;          // m-block
    const int nblk = bx * 128;
    const int tx = tid & 15;             // n tile
    const int ty = tid >> 4;             // m tile

    // A-load mapping: one float4 per thread (128 rows x 8 k)
    const int a_row = tid >> 1;
    const int a_k   = (tid & 1) * 4;
    const int m     = by * 128 + a_row;
    const float* arow;
    if (GATHER) {
        int w  = m / NTOK;
        int rr = m - w * NTOK;
        arow = (rr < NGT) ? (A    + (size_t)(w * NGT + rr) * CDIM)
                          : (Aavg + (size_t)(w >> 6)       * CDIM);
    } else {
        arow = A + (size_t)m * CDIM;
    }

    // B-load mapping: one float4 per thread (8 k x 128 n)
    const int b_k = tid >> 5;
    const int b_n = (tid & 31) * 4;
    const float* wptr = W + (size_t)b_k * N + nblk + b_n;

    float acc[8][8];
    #pragma unroll
    for (int i = 0; i < 8; i++)
        #pragma unroll
        for (int j = 0; j < 8; j++) acc[i][j] = 0.0f;

    for (int kt = 0; kt < 16; kt++) {
        float4 av = *(const float4*)(arow + kt * 8 + a_k);
        float4 bv = *(const float4*)(wptr + (size_t)kt * 8 * N);
        __syncthreads();
        As[a_k + 0][a_row] = av.x;
        As[a_k + 1][a_row] = av.y;
        As[a_k + 2][a_row] = av.z;
        As[a_k + 3][a_row] = av.w;
        *(float4*)&Bs[b_k][b_n] = bv;
        __syncthreads();
        #pragma unroll
        for (int k = 0; k < 8; k++) {
            float ar[8], br[8];
            *(float4*)(ar)     = *(const float4*)&As[k][ty * 8];
            *(float4*)(ar + 4) = *(const float4*)&As[k][ty * 8 + 4];
            *(float4*)(br)     = *(const float4*)&Bs[k][tx * 8];
            *(float4*)(br + 4) = *(const float4*)&Bs[k][tx * 8 + 4];
            #pragma unroll
            for (int i = 0; i < 8; i++)
                #pragma unroll
                for (int j = 0; j < 8; j++)
                    acc[i][j] += ar[i] * br[j];
        }
    }

    float* Cout;
    if (DST == 0)       Cout = g_Q;
    else if (DST == 1)  Cout = (bx == 0) ? g_Kw : g_Vw;
    else                Cout = (bx == 0) ? g_Kg : g_Vg;

    #pragma unroll
    for (int i = 0; i < 8; i++) {
        int row = by * 128 + ty * 8 + i;
        float* cp = Cout + (size_t)row * 128 + tx * 8;
        #pragma unroll
        for (int j = 0; j < 8; j++)
            cp[j] = (acc[i][j] + bias[nblk + tx * 8 + j]) * alpha;
    }
}

// ---------------- bias gather: g_bias[h][i][j] = table[rel_idx[i][j]][h] ----
__global__ void bias_build_kernel(const float* __restrict__ table,
                                  const int* __restrict__ ridx)
{
    int idx = blockIdx.x * 256 + threadIdx.x;
    if (idx < HEADS * NGT * NTOK) {
        int h  = idx / (NGT * NTOK);
        int ij = idx - h * (NGT * NTOK);
        g_bias[idx] = table[ridx[ij] * HEADS + h];
    }
}

// ---------------- window attention: one block per (window, head) -----------
// 128 threads. smem tiles, register-tiled 49x50 logits and 49x32 output.
__global__ void __launch_bounds__(128)
win_attn_kernel(const float* __restrict__ mask, float* __restrict__ out)
{
    const int w = blockIdx.x;
    const int h = blockIdx.y;
    const int tid = threadIdx.x;

    __shared__ float sq[56 * 32];      // rows 49..55 garbage (discarded)
    __shared__ float sk[64 * 33];      // padded stride 33
    __shared__ float sv[64 * 33];
    __shared__ float S [56 * 50];      // rows 49..55 scratch

    for (int idx = tid; idx < NGT * HD; idx += 128) {
        int i = idx >> 5, d = idx & 31;
        sq[i * 32 + d] = g_Q[(size_t)(w * NGT + i) * CDIM + h * HD + d];
    }
    for (int idx = tid; idx < NTOK * HD; idx += 128) {
        int i = idx >> 5, d = idx & 31;
        size_t off = (size_t)(w * NTOK + i) * CDIM + h * HD + d;
        sk[i * 33 + d] = g_Kw[off];
        sv[i * 33 + d] = g_Vw[off];
    }
    __syncthreads();

    const float* bptr = g_bias + h * (NGT * NTOK);
    const float* mptr = mask + (size_t)(w & 63) * (NGT * NTOK);

    // ---- logits S = q k^T + bias + mask : 8x16 thread grid, 7x4 tiles ----
    {
        const int c = tid & 15, r = tid >> 4;
        float acc[7][4];
        #pragma unroll
        for (int ii = 0; ii < 7; ii++)
            #pragma unroll
            for (int jj = 0; jj < 4; jj++) acc[ii][jj] = 0.0f;
        #pragma unroll 4
        for (int d = 0; d < 32; d++) {
            float a[7], b[4];
            #pragma unroll
            for (int ii = 0; ii < 7; ii++) a[ii] = sq[(r * 7 + ii) * 32 + d];
            #pragma unroll
            for (int jj = 0; jj < 4; jj++) b[jj] = sk[(c * 4 + jj) * 33 + d];
            #pragma unroll
            for (int ii = 0; ii < 7; ii++)
                #pragma unroll
                for (int jj = 0; jj < 4; jj++)
                    acc[ii][jj] += a[ii] * b[jj];
        }
        #pragma unroll
        for (int ii = 0; ii < 7; ii++) {
            int i = r * 7 + ii;
            #pragma unroll
            for (int jj = 0; jj < 4; jj++) {
                int j = c * 4 + jj;
                if (i < NGT && j < NTOK)
                    S[i * 50 + j] = acc[ii][jj] + bptr[i * 50 + j] + mptr[i * 50 + j];
            }
        }
    }
    __syncthreads();

    // ---- softmax per row ----
    if (tid < NGT) {
        float mx = -1e30f;
        for (int j = 0; j < NTOK; j++) mx = fmaxf(mx, S[tid * 50 + j]);
        float sum = 0.0f;
        for (int j = 0; j < NTOK; j++) {
            float e = expf(S[tid * 50 + j] - mx);
            S[tid * 50 + j] = e;
            sum += e;
        }
        float inv = 1.0f / sum;
        for (int j = 0; j < NTOK; j++) S[tid * 50 + j] *= inv;
    }
    __syncthreads();

    // ---- O = P @ v : 8x16 grid, 7x2 tiles ----
    {
        const int c = tid & 15, r = tid >> 4;
        float acc[7][2];
        #pragma unroll
        for (int ii = 0; ii < 7; ii++) { acc[ii][0] = 0.0f; acc[ii][1] = 0.0f; }
        #pragma unroll 2
        for (int j = 0; j < NTOK; j++) {
            float a[7], b[2];
            #pragma unroll
            for (int ii = 0; ii < 7; ii++) a[ii] = S[(r * 7 + ii) * 50 + j];
            b[0] = sv[j * 33 + c * 2 + 0];
            b[1] = sv[j * 33 + c * 2 + 1];
            #pragma unroll
            for (int ii = 0; ii < 7; ii++) {
                acc[ii][0] += a[ii] * b[0];
                acc[ii][1] += a[ii] * b[1];
            }
        }
        #pragma unroll
        for (int ii = 0; ii < 7; ii++) {
            int i = r * 7 + ii;
            if (i < NGT) {
                size_t base = (size_t)(w * NGT + i) * CDIM + h * HD + c * 2;
                out[base + 0] = acc[ii][0];
                out[base + 1] = acc[ii][1];
            }
        }
    }
}

// ---------------- global-token attention: one block per (image, head) ------
__global__ void __launch_bounds__(256)
glob_attn_kernel(const float* __restrict__ xavg, const float* __restrict__ Wq,
                 const float* __restrict__ bq, float* __restrict__ out)
{
    const int b = blockIdx.x;
    const int h = blockIdx.y;
    const int tid = threadIdx.x;

    __shared__ float qa[32];
    __shared__ float logits[NTPAT];
    __shared__ float red[256];

    if (tid < 32) {      // q_avg = xavg @ W_q + b_q  (NOT scaled)
        float acc = bq[h * HD + tid];
        const float* xr = xavg + (size_t)b * CDIM;
        for (int c = 0; c < CDIM; c++)
            acc += xr[c] * Wq[c * CDIM + h * HD + tid];
        qa[tid] = acc;
    }
    __syncthreads();

    const int warp = tid >> 5, lane = tid & 31;
    for (int mm = warp; mm < NTPAT; mm += 8) {
        float p = qa[lane] * g_Kg[(size_t)(b * NTPAT + mm) * CDIM + h * HD + lane];
        #pragma unroll
        for (int o = 16; o; o >>= 1) p += __shfl_down_sync(0xffffffffu, p, o);
        if (lane == 0) logits[mm] = p;
    }
    __syncthreads();

    float mx = -1e30f;
    for (int mm = tid; mm < NTPAT; mm += 256) mx = fmaxf(mx, logits[mm]);
    red[tid] = mx; __syncthreads();
    for (int s = 128; s; s >>= 1) { if (tid < s) red[tid] = fmaxf(red[tid], red[tid + s]); __syncthreads(); }
    mx = red[0]; __syncthreads();

    float sum = 0.0f;
    for (int mm = tid; mm < NTPAT; mm += 256) {
        float e = expf(logits[mm] - mx);
        logits[mm] = e;
        sum += e;
    }
    red[tid] = sum; __syncthreads();
    for (int s = 128; s; s >>= 1) { if (tid < s) red[tid] += red[tid + s]; __syncthreads(); }
    sum = red[0];
    __syncthreads();

    const int d = tid & 31, part = tid >> 5;        // 8 parts x 392 patches
    float acc = 0.0f;
    for (int mm = part * 392; mm < (part + 1) * 392; mm++)
        acc += logits[mm] * g_Vg[(size_t)(b * NTPAT + mm) * CDIM + h * HD + d];
    red[tid] = acc;
    __syncthreads();
    if (tid < 32) {
        float a = 0.0f;
        #pragma unroll
        for (int p = 0; p < 8; p++) a += red[p * 32 + tid];
        out[(size_t)b * CDIM + h * HD + tid] = a / sum;
    }
}

// ---------------- launch ----------------
extern "C" void kernel_launch(void* const* d_in, const int* in_sizes, int n_in,
                              void* d_out, int out_size)
{
    const float* x      = (const float*)d_in[0];
    const float* xtotal = (const float*)d_in[1];
    const float* xavg   = (const float*)d_in[2];
    const float* mask   = (const float*)d_in[3];
    const float* Wq     = (const float*)d_in[4];
    const float* bq     = (const float*)d_in[5];
    const float* Wkv    = (const float*)d_in[6];
    const float* bkv    = (const float*)d_in[7];
    const float* btab   = (const float*)d_in[8];
    const int*   ridx   = (const int*)d_in[9];

    float* out     = (float*)d_out;
    float* out_avg = out + (size_t)200704u * 128u;   // x_out then xavg_out

    bias_build_kernel<<<(HEADS * NGT * NTOK + 255) / 256, 256>>>(btab, ridx);

    // q = (x @ W_q + b_q) * scale     : M = 200704
    sgemm_kernel<0, 0><<<dim3(1, 1568), 256>>>(x, nullptr, Wq, bq, 128, WQ_SCALE);
    // window kv = concat(x, xavg) @ W_kv + b_kv : M = 204800, N = 256
    sgemm_kernel<1, 1><<<dim3(2, 1600), 256>>>(x, xavg, Wkv, bkv, 256, 1.0f);
    // global kv = xtotal @ W_kv + b_kv : M = 200704, N = 256
    sgemm_kernel<0, 2><<<dim3(2, 1568), 256>>>(xtotal, nullptr, Wkv, bkv, 256, 1.0f);

    win_attn_kernel<<<dim3(NWIN, HEADS), 128>>>(mask, out);
    glob_attn_kernel<<<dim3(BIMG, HEADS), 256>>>(xavg, Wq, bq, out_avg);
}

// round 3
// speedup vs baseline: 1.7483x; 1.7483x over previous
#include <cuda_runtime.h>

// ---------------- problem dims ----------------
#define NWIN   4096
#define NGT    49
#define NTOK   50
#define CDIM   128
#define HEADS  4
#define HD     32
#define BIMG   64
#define NTPAT  3136
#define WQ_SCALE 0.17677669529663687f   // 32^-0.5

// ---------------- device scratch ----------------
__device__ float g_Q [200704u * 128u];
__device__ float g_Kw[204800u * 128u];
__device__ float g_Vw[204800u * 128u];
__device__ float g_Kg[200704u * 128u];
__device__ float g_Vg[200704u * 128u];
__device__ float g_bias[HEADS * NGT * NTOK];

__device__ __forceinline__ unsigned f2tf(float f) {
    unsigned r;
    asm("cvt.rna.tf32.f32 %0, %1;" : "=r"(r) : "f"(f));
    return r;
}

__device__ __forceinline__ void mma_tf32(float& c0, float& c1, float& c2, float& c3,
                                         unsigned a0, unsigned a1, unsigned a2, unsigned a3,
                                         unsigned b0, unsigned b1)
{
    asm volatile("mma.sync.aligned.m16n8k8.row.col.f32.tf32.tf32.f32 "
                 "{%0,%1,%2,%3}, {%4,%5,%6,%7}, {%8,%9}, {%0,%1,%2,%3};"
                 : "+f"(c0), "+f"(c1), "+f"(c2), "+f"(c3)
                 : "r"(a0), "r"(a1), "r"(a2), "r"(a3), "r"(b0), "r"(b1));
}

// ---------------- TF32 tensor-core GEMM ----------------
// C[M,128|256] = (A[M,128] @ W[128,N] + b) * alpha
// Block 128x128, B panel (full K) resident K-major [k][136], A double-buffered [m][36].
// 8 warps = 2(m) x 4(n); warp tile 64x32 (4x4 m16n8k8 frags).
#define SB_STRIDE 136
#define SA_STRIDE 36
#define SB_FLOATS (128 * SB_STRIDE)
#define SA_FLOATS (128 * SA_STRIDE)
#define GEMM_SMEM ((SB_FLOATS + 2 * SA_FLOATS) * 4)

template<int GATHER, int DST>
__global__ void __launch_bounds__(256, 1)
mma_gemm(const float* __restrict__ A, const float* __restrict__ Aavg,
         const float* __restrict__ W, const float* __restrict__ bias,
         int N, float alpha)
{
    extern __shared__ float smem[];
    float* sB = smem;                    // [128 k][136]
    float* sA = smem + SB_FLOATS;        // 2 x [128 m][36]

    const int tid  = threadIdx.x;
    const int lane = tid & 31;
    const int warp = tid >> 5;
    const int wm   = warp >> 2;          // 0..1
    const int wn   = warp & 3;           // 0..3
    const int g4   = lane >> 2;          // groupID 0..7
    const int t4   = lane & 3;           // 0..3
    const int nblk = blockIdx.x * 128;
    const int by   = blockIdx.y;

    // ---- A row pointer (fixed per thread across k-tiles) ----
    const int a_row = tid >> 1;          // 0..127
    const int a_half = (tid & 1) * 16;   // 0 or 16 (k offset)
    const int m = by * 128 + a_row;
    const float* arow;
    if (GATHER) {
        int w  = m / NTOK;
        int rr = m - w * NTOK;
        arow = (rr < NGT) ? (A    + (size_t)(w * NGT + rr) * CDIM)
                          : (Aavg + (size_t)(w >> 6)       * CDIM);
    } else {
        arow = A + (size_t)m * CDIM;
    }

    // ---- load full B panel (128x128 tf32), coalesced, conflict-free ----
    #pragma unroll
    for (int i = 0; i < 16; i++) {
        int idx = tid + 256 * i;         // 0..4095
        int kk  = idx >> 5;              // 0..127
        int n4  = (idx & 31) << 2;       // 0..124
        float4 v = *(const float4*)(W + (size_t)kk * N + nblk + n4);
        float4 t;
        t.x = __uint_as_float(f2tf(v.x));
        t.y = __uint_as_float(f2tf(v.y));
        t.z = __uint_as_float(f2tf(v.z));
        t.w = __uint_as_float(f2tf(v.w));
        *(float4*)&sB[kk * SB_STRIDE + n4] = t;
    }

    // ---- prologue: A tile 0 ----
    float4 areg[4];
    #pragma unroll
    for (int j = 0; j < 4; j++)
        areg[j] = *(const float4*)(arow + a_half + 4 * j);
    {
        float* dst = sA + a_row * SA_STRIDE + a_half;
        #pragma unroll
        for (int j = 0; j < 4; j++) {
            float4 t;
            t.x = __uint_as_float(f2tf(areg[j].x));
            t.y = __uint_as_float(f2tf(areg[j].y));
            t.z = __uint_as_float(f2tf(areg[j].z));
            t.w = __uint_as_float(f2tf(areg[j].w));
            *(float4*)(dst + 4 * j) = t;
        }
    }
    __syncthreads();

    float acc[4][4][4];
    #pragma unroll
    for (int mf = 0; mf < 4; mf++)
        #pragma unroll
        for (int nf = 0; nf < 4; nf++)
            #pragma unroll
            for (int c = 0; c < 4; c++) acc[mf][nf][c] = 0.0f;

    const int a_m0 = wm * 64;
    const int b_n0 = wn * 32;

    for (int kt = 0; kt < 4; kt++) {
        if (kt < 3) {
            #pragma unroll
            for (int j = 0; j < 4; j++)
                areg[j] = *(const float4*)(arow + (kt + 1) * 32 + a_half + 4 * j);
        }
        const float* As = sA + (kt & 1) * SA_FLOATS;
        #pragma unroll
        for (int ks = 0; ks < 4; ks++) {
            const int k0 = ks * 8;
            unsigned a[4][4], b[4][2];
            #pragma unroll
            for (int mf = 0; mf < 4; mf++) {
                const float* ap = As + (a_m0 + mf * 16 + g4) * SA_STRIDE + k0 + t4;
                a[mf][0] = __float_as_uint(ap[0]);
                a[mf][1] = __float_as_uint(ap[8 * SA_STRIDE]);
                a[mf][2] = __float_as_uint(ap[4]);
                a[mf][3] = __float_as_uint(ap[8 * SA_STRIDE + 4]);
            }
            #pragma unroll
            for (int nf = 0; nf < 4; nf++) {
                const float* bp = sB + (kt * 32 + k0 + t4) * SB_STRIDE + b_n0 + nf * 8 + g4;
                b[nf][0] = __float_as_uint(bp[0]);
                b[nf][1] = __float_as_uint(bp[4 * SB_STRIDE]);
            }
            #pragma unroll
            for (int mf = 0; mf < 4; mf++)
                #pragma unroll
                for (int nf = 0; nf < 4; nf++)
                    mma_tf32(acc[mf][nf][0], acc[mf][nf][1], acc[mf][nf][2], acc[mf][nf][3],
                             a[mf][0], a[mf][1], a[mf][2], a[mf][3],
                             b[nf][0], b[nf][1]);
        }
        if (kt < 3) {
            __syncthreads();
            float* dst = sA + ((kt + 1) & 1) * SA_FLOATS + a_row * SA_STRIDE + a_half;
            #pragma unroll
            for (int j = 0; j < 4; j++) {
                float4 t;
                t.x = __uint_as_float(f2tf(areg[j].x));
                t.y = __uint_as_float(f2tf(areg[j].y));
                t.z = __uint_as_float(f2tf(areg[j].z));
                t.w = __uint_as_float(f2tf(areg[j].w));
                *(float4*)(dst + 4 * j) = t;
            }
            __syncthreads();
        }
    }

    // ---- epilogue: (acc + bias) * alpha ----
    float* Cout;
    if (DST == 0)       Cout = g_Q;
    else if (DST == 1)  Cout = (blockIdx.x == 0) ? g_Kw : g_Vw;
    else                Cout = (blockIdx.x == 0) ? g_Kg : g_Vg;

    #pragma unroll
    for (int mf = 0; mf < 4; mf++) {
        int row0 = by * 128 + a_m0 + mf * 16 + g4;
        #pragma unroll
        for (int nf = 0; nf < 4; nf++) {
            int ncol = b_n0 + nf * 8 + 2 * t4;            // local column (0..127)
            float bb0 = bias[nblk + ncol];
            float bb1 = bias[nblk + ncol + 1];
            float2 v0, v1;
            v0.x = (acc[mf][nf][0] + bb0) * alpha;
            v0.y = (acc[mf][nf][1] + bb1) * alpha;
            v1.x = (acc[mf][nf][2] + bb0) * alpha;
            v1.y = (acc[mf][nf][3] + bb1) * alpha;
            *(float2*)(Cout + (size_t)row0 * 128 + ncol)       = v0;
            *(float2*)(Cout + (size_t)(row0 + 8) * 128 + ncol) = v1;
        }
    }
}

// ---------------- bias gather ----------------
__global__ void bias_build_kernel(const float* __restrict__ table,
                                  const int* __restrict__ ridx)
{
    int idx = blockIdx.x * 256 + threadIdx.x;
    if (idx < HEADS * NGT * NTOK) {
        int h  = idx / (NGT * NTOK);
        int ij = idx - h * (NGT * NTOK);
        g_bias[idx] = table[ridx[ij] * HEADS + h];
    }
}

// ---------------- window attention ----------------
__global__ void __launch_bounds__(128)
win_attn_kernel(const float* __restrict__ mask, float* __restrict__ out)
{
    const int w = blockIdx.x;
    const int h = blockIdx.y;
    const int tid = threadIdx.x;

    __shared__ float sq[56 * 32];
    __shared__ float sk[64 * 33];
    __shared__ float sv[64 * 33];
    __shared__ float S [56 * 50];

    for (int idx = tid; idx < NGT * HD; idx += 128) {
        int i = idx >> 5, d = idx & 31;
        sq[i * 32 + d] = g_Q[(size_t)(w * NGT + i) * CDIM + h * HD + d];
    }
    for (int idx = tid; idx < NTOK * HD; idx += 128) {
        int i = idx >> 5, d = idx & 31;
        size_t off = (size_t)(w * NTOK + i) * CDIM + h * HD + d;
        sk[i * 33 + d] = g_Kw[off];
        sv[i * 33 + d] = g_Vw[off];
    }
    __syncthreads();

    const float* bptr = g_bias + h * (NGT * NTOK);
    const float* mptr = mask + (size_t)(w & 63) * (NGT * NTOK);

    {
        const int c = tid & 15, r = tid >> 4;
        float acc[7][4];
        #pragma unroll
        for (int ii = 0; ii < 7; ii++)
            #pragma unroll
            for (int jj = 0; jj < 4; jj++) acc[ii][jj] = 0.0f;
        #pragma unroll 4
        for (int d = 0; d < 32; d++) {
            float a[7], b[4];
            #pragma unroll
            for (int ii = 0; ii < 7; ii++) a[ii] = sq[(r * 7 + ii) * 32 + d];
            #pragma unroll
            for (int jj = 0; jj < 4; jj++) b[jj] = sk[(c * 4 + jj) * 33 + d];
            #pragma unroll
            for (int ii = 0; ii < 7; ii++)
                #pragma unroll
                for (int jj = 0; jj < 4; jj++)
                    acc[ii][jj] += a[ii] * b[jj];
        }
        #pragma unroll
        for (int ii = 0; ii < 7; ii++) {
            int i = r * 7 + ii;
            #pragma unroll
            for (int jj = 0; jj < 4; jj++) {
                int j = c * 4 + jj;
                if (i < NGT && j < NTOK)
                    S[i * 50 + j] = acc[ii][jj] + bptr[i * 50 + j] + mptr[i * 50 + j];
            }
        }
    }
    __syncthreads();

    if (tid < NGT) {
        float mx = -1e30f;
        for (int j = 0; j < NTOK; j++) mx = fmaxf(mx, S[tid * 50 + j]);
        float sum = 0.0f;
        for (int j = 0; j < NTOK; j++) {
            float e = expf(S[tid * 50 + j] - mx);
            S[tid * 50 + j] = e;
            sum += e;
        }
        float inv = 1.0f / sum;
        for (int j = 0; j < NTOK; j++) S[tid * 50 + j] *= inv;
    }
    __syncthreads();

    {
        const int c = tid & 15, r = tid >> 4;
        float acc[7][2];
        #pragma unroll
        for (int ii = 0; ii < 7; ii++) { acc[ii][0] = 0.0f; acc[ii][1] = 0.0f; }
        #pragma unroll 2
        for (int j = 0; j < NTOK; j++) {
            float a[7], b[2];
            #pragma unroll
            for (int ii = 0; ii < 7; ii++) a[ii] = S[(r * 7 + ii) * 50 + j];
            b[0] = sv[j * 33 + c * 2 + 0];
            b[1] = sv[j * 33 + c * 2 + 1];
            #pragma unroll
            for (int ii = 0; ii < 7; ii++) {
                acc[ii][0] += a[ii] * b[0];
                acc[ii][1] += a[ii] * b[1];
            }
        }
        #pragma unroll
        for (int ii = 0; ii < 7; ii++) {
            int i = r * 7 + ii;
            if (i < NGT) {
                size_t base = (size_t)(w * NGT + i) * CDIM + h * HD + c * 2;
                out[base + 0] = acc[ii][0];
                out[base + 1] = acc[ii][1];
            }
        }
    }
}

// ---------------- global-token attention ----------------
__global__ void __launch_bounds__(256)
glob_attn_kernel(const float* __restrict__ xavg, const float* __restrict__ Wq,
                 const float* __restrict__ bq, float* __restrict__ out)
{
    const int b = blockIdx.x;
    const int h = blockIdx.y;
    const int tid = threadIdx.x;

    __shared__ float qa[32];
    __shared__ float logits[NTPAT];
    __shared__ float red[256];

    if (tid < 32) {
        float acc = bq[h * HD + tid];
        const float* xr = xavg + (size_t)b * CDIM;
        for (int c = 0; c < CDIM; c++)
            acc += xr[c] * Wq[c * CDIM + h * HD + tid];
        qa[tid] = acc;
    }
    __syncthreads();

    const int warp = tid >> 5, lane = tid & 31;
    for (int mm = warp; mm < NTPAT; mm += 8) {
        float p = qa[lane] * g_Kg[(size_t)(b * NTPAT + mm) * CDIM + h * HD + lane];
        #pragma unroll
        for (int o = 16; o; o >>= 1) p += __shfl_down_sync(0xffffffffu, p, o);
        if (lane == 0) logits[mm] = p;
    }
    __syncthreads();

    float mx = -1e30f;
    for (int mm = tid; mm < NTPAT; mm += 256) mx = fmaxf(mx, logits[mm]);
    red[tid] = mx; __syncthreads();
    for (int s = 128; s; s >>= 1) { if (tid < s) red[tid] = fmaxf(red[tid], red[tid + s]); __syncthreads(); }
    mx = red[0]; __syncthreads();

    float sum = 0.0f;
    for (int mm = tid; mm < NTPAT; mm += 256) {
        float e = expf(logits[mm] - mx);
        logits[mm] = e;
        sum += e;
    }
    red[tid] = sum; __syncthreads();
    for (int s = 128; s; s >>= 1) { if (tid < s) red[tid] += red[tid + s]; __syncthreads(); }
    sum = red[0];
    __syncthreads();

    const int d = tid & 31, part = tid >> 5;
    float acc = 0.0f;
    for (int mm = part * 392; mm < (part + 1) * 392; mm++)
        acc += logits[mm] * g_Vg[(size_t)(b * NTPAT + mm) * CDIM + h * HD + d];
    red[tid] = acc;
    __syncthreads();
    if (tid < 32) {
        float a = 0.0f;
        #pragma unroll
        for (int p = 0; p < 8; p++) a += red[p * 32 + tid];
        out[(size_t)b * CDIM + h * HD + tid] = a / sum;
    }
}

// ---------------- launch ----------------
extern "C" void kernel_launch(void* const* d_in, const int* in_sizes, int n_in,
                              void* d_out, int out_size)
{
    const float* x      = (const float*)d_in[0];
    const float* xtotal = (const float*)d_in[1];
    const float* xavg   = (const float*)d_in[2];
    const float* mask   = (const float*)d_in[3];
    const float* Wq     = (const float*)d_in[4];
    const float* bq     = (const float*)d_in[5];
    const float* Wkv    = (const float*)d_in[6];
    const float* bkv    = (const float*)d_in[7];
    const float* btab   = (const float*)d_in[8];
    const int*   ridx   = (const int*)d_in[9];

    float* out     = (float*)d_out;
    float* out_avg = out + (size_t)200704u * 128u;

    static bool attr_done = false;
    // cudaFuncSetAttribute is idempotent host-side metadata, safe pre-capture
    cudaFuncSetAttribute(mma_gemm<0, 0>, cudaFuncAttributeMaxDynamicSharedMemorySize, GEMM_SMEM);
    cudaFuncSetAttribute(mma_gemm<1, 1>, cudaFuncAttributeMaxDynamicSharedMemorySize, GEMM_SMEM);
    cudaFuncSetAttribute(mma_gemm<0, 2>, cudaFuncAttributeMaxDynamicSharedMemorySize, GEMM_SMEM);
    (void)attr_done;

    bias_build_kernel<<<(HEADS * NGT * NTOK + 255) / 256, 256>>>(btab, ridx);

    // q = (x @ W_q + b_q) * scale : M = 200704, N = 128
    mma_gemm<0, 0><<<dim3(1, 1568), 256, GEMM_SMEM>>>(x, nullptr, Wq, bq, 128, WQ_SCALE);
    // window kv = concat(x, xavg) @ W_kv + b_kv : M = 204800, N = 256
    mma_gemm<1, 1><<<dim3(2, 1600), 256, GEMM_SMEM>>>(x, xavg, Wkv, bkv, 256, 1.0f);
    // global kv = xtotal @ W_kv + b_kv : M = 200704, N = 256
    mma_gemm<0, 2><<<dim3(2, 1568), 256, GEMM_SMEM>>>(xtotal, nullptr, Wkv, bkv, 256, 1.0f);

    win_attn_kernel<<<dim3(NWIN, HEADS), 128>>>(mask, out);
    glob_attn_kernel<<<dim3(BIMG, HEADS), 256>>>(xavg, Wq, bq, out_avg);
}